// round 2
// baseline (speedup 1.0000x reference)
#include <cuda_runtime.h>
#include <cuda_bf16.h>
#include <cstdint>

// Problem constants (fixed for this bench)
#define BATCH 2
#define NPTS  250000
#define MPTS  (BATCH * NPTS)      // 500000
#define CCH   32
#define SDIM  128
#define S2    (SDIM * SDIM)
#define S3    (SDIM * SDIM * SDIM)

// ---------------- static device scratch (no allocations allowed) ----------------
__device__ int   g_grid[BATCH * S3];          // 16.8 MB voxel -> point index, -1 empty
__device__ int   g_nbrs[(size_t)MPTS * 27];   // 54 MB packed (idx<<5)|k, compacted
__device__ int   g_cnt [MPTS];
__device__ float g_x1  [(size_t)MPTS * CCH];  // 64 MB intermediate activations
__device__ float g_x2  [(size_t)MPTS * CCH];
// Pre-transposed weights: Wp4[layer][k][q][cin] (float4) = W[layer][k][cin][4q..4q+3]
__device__ float4 g_Wp4[3 * 27 * 8 * CCH];    // 3 * 6912 float4

// ---------------- kernels ----------------

__global__ void scatter_kernel(const int* __restrict__ coords) {
    int m = blockIdx.x * blockDim.x + threadIdx.x;
    if (m >= MPTS) return;
    int b = (m >= NPTS) ? 1 : 0;
    const int* c = coords + (size_t)m * 3;
    int x = c[0], y = c[1], z = c[2];
    g_grid[b * S3 + x * S2 + y * SDIM + z] = m;
}

__global__ void build_nbrs_kernel(const int* __restrict__ coords) {
    int m = blockIdx.x * blockDim.x + threadIdx.x;
    if (m >= MPTS) return;
    int b = (m >= NPTS) ? 1 : 0;
    const int* c = coords + (size_t)m * 3;
    int x = c[0], y = c[1], z = c[2];
    const int* gridb = g_grid + b * S3;
    int cnt = 0;
    int* out = g_nbrs + (size_t)m * 27;
    #pragma unroll
    for (int dx = -1; dx <= 1; dx++) {
        int nx = x + dx;
        bool okx = (nx >= 0) & (nx < SDIM);
        #pragma unroll
        for (int dy = -1; dy <= 1; dy++) {
            int ny = y + dy;
            bool oky = okx & (ny >= 0) & (ny < SDIM);
            #pragma unroll
            for (int dz = -1; dz <= 1; dz++) {
                int nz = z + dz;
                if (oky & (nz >= 0) & (nz < SDIM)) {
                    int idx = gridb[nx * S2 + ny * SDIM + nz];
                    if (idx >= 0) {
                        int k = (dx + 1) * 9 + (dy + 1) * 3 + (dz + 1);
                        out[cnt++] = (idx << 5) | k;
                    }
                }
            }
        }
    }
    g_cnt[m] = cnt;
}

// Transpose W[k][cin][cout] (fp32) -> Wp4[k][q][cin] (float4 over cout 4q..4q+3)
__global__ void prep_w_kernel(const float* __restrict__ W1,
                              const float* __restrict__ W2,
                              const float* __restrict__ W3) {
    int t = blockIdx.x * blockDim.x + threadIdx.x;
    const int PER = 27 * 8 * CCH;  // 6912
    if (t >= 3 * PER) return;
    int layer = t / PER;
    int r = t % PER;
    int k   = r / (8 * CCH);
    int q   = (r / CCH) & 7;
    int cin = r & (CCH - 1);
    const float* W = (layer == 0) ? W1 : (layer == 1) ? W2 : W3;
    const float4* Wsrc4 = reinterpret_cast<const float4*>(W);
    // src flat float index: k*1024 + cin*32 + 4q  -> float4 index k*256 + cin*8 + q
    g_Wp4[t] = Wsrc4[k * 256 + cin * 8 + q];
}

// Warp per point; lane = cin. part[cout] per lane, butterfly-reduced at the end.
template <bool RELU>
__global__ void layer_kernel(const float* __restrict__ fin,
                             float* __restrict__ fout,
                             const float4* __restrict__ Wp4) {
    int warp = (blockIdx.x * blockDim.x + threadIdx.x) >> 5;
    int lane = threadIdx.x & 31;
    if (warp >= MPTS) return;
    int m = warp;

    int cnt = g_cnt[m];                                   // uniform broadcast
    int ent = g_nbrs[(size_t)m * 27 + min(lane, 26)];     // coalesced 108B

    float part[32];
    #pragma unroll
    for (int i = 0; i < 32; i++) part[i] = 0.f;

    for (int j = 0; j < cnt; j++) {
        int pk  = __shfl_sync(0xffffffffu, ent, j);
        int idx = pk >> 5;
        int k   = pk & 31;
        float fv = __ldg(fin + (size_t)idx * CCH + lane); // 128B coalesced row
        const float4* wr = Wp4 + k * 256;                 // 8*32 float4 per offset
        #pragma unroll
        for (int q = 0; q < 8; q++) {
            float4 w = __ldg(wr + q * 32 + lane);         // 512B contiguous per LDG.128
            part[4 * q + 0] += fv * w.x;
            part[4 * q + 1] += fv * w.y;
            part[4 * q + 2] += fv * w.z;
            part[4 * q + 3] += fv * w.w;
        }
    }

    // Butterfly halving reduction: lane l ends with sum over lanes of part[l]
    #pragma unroll
    for (int off = 16; off >= 1; off >>= 1) {
        bool hi = (lane & off) != 0;
        #pragma unroll
        for (int i = 0; i < off; i++) {
            float send = hi ? part[i] : part[i + off];
            float r = __shfl_xor_sync(0xffffffffu, send, off);
            part[i] = (hi ? part[i + off] : part[i]) + r;
        }
    }
    float v = part[0];
    if (RELU) v = fmaxf(v, 0.f);
    fout[(size_t)m * CCH + lane] = v;
}

// ---------------- launch ----------------
extern "C" void kernel_launch(void* const* d_in, const int* in_sizes, int n_in,
                              void* d_out, int out_size) {
    const float* features = (const float*)d_in[0];
    const int*   coords   = (const int*)d_in[1];
    // Last three inputs are W1, W2, W3 (27648 floats each)
    const float* W1 = (const float*)d_in[n_in - 3];
    const float* W2 = (const float*)d_in[n_in - 2];
    const float* W3 = (const float*)d_in[n_in - 1];
    float* out = (float*)d_out;

    // No static caching: resolve scratch symbol addresses every call (host-side
    // query, graph-capture-safe, deterministic).
    int*    grid_ptr = nullptr;
    float*  x1_ptr   = nullptr;
    float*  x2_ptr   = nullptr;
    float4* wp_ptr   = nullptr;
    cudaGetSymbolAddress((void**)&grid_ptr, g_grid);
    cudaGetSymbolAddress((void**)&x1_ptr,   g_x1);
    cudaGetSymbolAddress((void**)&x2_ptr,   g_x2);
    cudaGetSymbolAddress((void**)&wp_ptr,   g_Wp4);

    // 1) clear grid to -1
    cudaMemsetAsync(grid_ptr, 0xFF, (size_t)BATCH * S3 * sizeof(int));

    // 2) scatter point indices
    {
        int threads = 256, blocks = (MPTS + threads - 1) / threads;
        scatter_kernel<<<blocks, threads>>>(coords);
    }
    // 3) compacted neighbor lists (reused by all 3 layers)
    {
        int threads = 256, blocks = (MPTS + threads - 1) / threads;
        build_nbrs_kernel<<<blocks, threads>>>(coords);
    }
    // 4) weight transpose for coalesced inner loop
    {
        int total = 3 * 27 * 8 * CCH;
        int threads = 256, blocks = (total + threads - 1) / threads;
        prep_w_kernel<<<blocks, threads>>>(W1, W2, W3);
    }
    // 5) three conv layers, warp per point
    {
        int threads = 256;                       // 8 warps -> 8 points per block
        int blocks = (MPTS * 32 + threads - 1) / threads;
        layer_kernel<true ><<<blocks, threads>>>(features, x1_ptr, wp_ptr + 0 * 27 * 256);
        layer_kernel<true ><<<blocks, threads>>>(x1_ptr,   x2_ptr, wp_ptr + 1 * 27 * 256);
        layer_kernel<false><<<blocks, threads>>>(x2_ptr,   out,    wp_ptr + 2 * 27 * 256);
    }
    (void)in_sizes; (void)out_size;
}

// round 5
// speedup vs baseline: 1.0483x; 1.0483x over previous
#include <cuda_runtime.h>
#include <cuda_bf16.h>
#include <cstdint>

// Problem constants (fixed for this bench)
#define BATCH 2
#define NPTS  250000
#define MPTS  (BATCH * NPTS)      // 500000
#define CCH   32
#define SDIM  128
#define S2    (SDIM * SDIM)
#define S3    (SDIM * SDIM * SDIM)

#define TILE   64                         // points per warp-tile
#define NTILES ((MPTS + TILE - 1) / TILE) // 7813
#define NK     27

// ---------------- static device scratch (no allocations allowed) ----------------
__device__ int   g_grid [BATCH * S3];                    // 16.8 MB voxel -> point idx, -1 empty
__device__ int   g_tcnt [NTILES * NK];                   // pairs per (tile,k)
__device__ int   g_tpairs[(size_t)NTILES * NK * TILE];   // 54 MB: (idx<<6)|p_local, k-grouped
__device__ float g_x1   [(size_t)MPTS * CCH];            // 64 MB intermediates
__device__ float g_x2   [(size_t)MPTS * CCH];

// ---------------- prep kernels ----------------

__global__ void scatter_kernel(const int* __restrict__ coords) {
    int m = blockIdx.x * blockDim.x + threadIdx.x;
    if (m >= MPTS) return;
    int b = (m >= NPTS) ? 1 : 0;
    const int* c = coords + (size_t)m * 3;
    g_grid[b * S3 + c[0] * S2 + c[1] * SDIM + c[2]] = m;
}

// Bin pairs by (tile, k). Capacity per bucket is exactly TILE since each point
// contributes at most one pair per offset k.
__global__ void build_pairs_kernel(const int* __restrict__ coords) {
    int m = blockIdx.x * blockDim.x + threadIdx.x;
    if (m >= MPTS) return;
    int b = (m >= NPTS) ? 1 : 0;
    const int* c = coords + (size_t)m * 3;
    int x = c[0], y = c[1], z = c[2];
    const int* gridb = g_grid + b * S3;
    int tile = m >> 6;
    int pl   = m & (TILE - 1);
    #pragma unroll
    for (int dx = -1; dx <= 1; dx++) {
        int nx = x + dx;
        if (nx < 0 || nx >= SDIM) continue;
        #pragma unroll
        for (int dy = -1; dy <= 1; dy++) {
            int ny = y + dy;
            if (ny < 0 || ny >= SDIM) continue;
            #pragma unroll
            for (int dz = -1; dz <= 1; dz++) {
                int nz = z + dz;
                if (nz < 0 || nz >= SDIM) continue;
                int idx = gridb[nx * S2 + ny * SDIM + nz];
                if (idx >= 0) {
                    int k = (dx + 1) * 9 + (dy + 1) * 3 + (dz + 1);
                    int key  = tile * NK + k;
                    int slot = atomicAdd(&g_tcnt[key], 1);
                    g_tpairs[(size_t)key * TILE + slot] = (idx << 6) | pl;
                }
            }
        }
    }
}

// ---------------- layer kernel ----------------
// 4 warps/block, warp = one 64-point tile. lane = cout.
// W_k register-resident per k; f-rows via uniform-address LDG (1 wavefront each);
// accumulators in smem (dynamic p indexing).
template <bool RELU>
__global__ void __launch_bounds__(128, 4)
layer_kernel(const float* __restrict__ fin,
             float* __restrict__ fout,
             const float* __restrict__ W) {   // [27][32][32] as in reference
    __shared__ float acc_s[4][TILE * CCH];    // 32 KB

    int wid  = threadIdx.x >> 5;
    int lane = threadIdx.x & 31;
    int tile = blockIdx.x * 4 + wid;
    if (tile >= NTILES) return;

    float* acc = acc_s[wid];
    #pragma unroll
    for (int i = 0; i < TILE; i++) acc[i * CCH + lane] = 0.f;

    for (int k = 0; k < NK; k++) {
        int key  = tile * NK + k;
        int cntk = __ldg(&g_tcnt[key]);
        if (cntk == 0) continue;

        // W_k[cin][lane] -> registers (coalesced 128B per cin)
        float Wreg[CCH];
        const float* wk = W + k * (CCH * CCH) + lane;
        #pragma unroll
        for (int cin = 0; cin < CCH; cin++) Wreg[cin] = __ldg(wk + cin * CCH);

        const int* pb = g_tpairs + (size_t)key * TILE;
        int ent0 = __ldg(pb + lane);
        int ent1 = (cntk > 32) ? __ldg(pb + 32 + lane) : 0;

        int j = 0;
        // 2 pairs per iteration for f-load MLP (p0 != p1 guaranteed within a k)
        for (; j + 1 < cntk; j += 2) {
            int lo0 = __shfl_sync(0xffffffffu, ent0, j & 31);
            int hi0 = __shfl_sync(0xffffffffu, ent1, j & 31);
            int e0  = (j < 32) ? lo0 : hi0;
            int lo1 = __shfl_sync(0xffffffffu, ent0, (j + 1) & 31);
            int hi1 = __shfl_sync(0xffffffffu, ent1, (j + 1) & 31);
            int e1  = (j + 1 < 32) ? lo1 : hi1;

            const float4* fr0 = (const float4*)(fin + (size_t)(e0 >> 6) * CCH);
            const float4* fr1 = (const float4*)(fin + (size_t)(e1 >> 6) * CCH);
            float4 a0 = __ldg(fr0 + 0), a1 = __ldg(fr0 + 1), a2 = __ldg(fr0 + 2), a3 = __ldg(fr0 + 3);
            float4 a4 = __ldg(fr0 + 4), a5 = __ldg(fr0 + 5), a6 = __ldg(fr0 + 6), a7 = __ldg(fr0 + 7);
            float4 b0 = __ldg(fr1 + 0), b1 = __ldg(fr1 + 1), b2 = __ldg(fr1 + 2), b3 = __ldg(fr1 + 3);
            float4 b4 = __ldg(fr1 + 4), b5 = __ldg(fr1 + 5), b6 = __ldg(fr1 + 6), b7 = __ldg(fr1 + 7);

            float t0, t1, t2, t3, u0, u1, u2, u3;
            t0  = a0.x * Wreg[0];  t1  = a0.y * Wreg[1];  t2  = a0.z * Wreg[2];  t3  = a0.w * Wreg[3];
            t0 += a1.x * Wreg[4];  t1 += a1.y * Wreg[5];  t2 += a1.z * Wreg[6];  t3 += a1.w * Wreg[7];
            t0 += a2.x * Wreg[8];  t1 += a2.y * Wreg[9];  t2 += a2.z * Wreg[10]; t3 += a2.w * Wreg[11];
            t0 += a3.x * Wreg[12]; t1 += a3.y * Wreg[13]; t2 += a3.z * Wreg[14]; t3 += a3.w * Wreg[15];
            t0 += a4.x * Wreg[16]; t1 += a4.y * Wreg[17]; t2 += a4.z * Wreg[18]; t3 += a4.w * Wreg[19];
            t0 += a5.x * Wreg[20]; t1 += a5.y * Wreg[21]; t2 += a5.z * Wreg[22]; t3 += a5.w * Wreg[23];
            t0 += a6.x * Wreg[24]; t1 += a6.y * Wreg[25]; t2 += a6.z * Wreg[26]; t3 += a6.w * Wreg[27];
            t0 += a7.x * Wreg[28]; t1 += a7.y * Wreg[29]; t2 += a7.z * Wreg[30]; t3 += a7.w * Wreg[31];
            u0  = b0.x * Wreg[0];  u1  = b0.y * Wreg[1];  u2  = b0.z * Wreg[2];  u3  = b0.w * Wreg[3];
            u0 += b1.x * Wreg[4];  u1 += b1.y * Wreg[5];  u2 += b1.z * Wreg[6];  u3 += b1.w * Wreg[7];
            u0 += b2.x * Wreg[8];  u1 += b2.y * Wreg[9];  u2 += b2.z * Wreg[10]; u3 += b2.w * Wreg[11];
            u0 += b3.x * Wreg[12]; u1 += b3.y * Wreg[13]; u2 += b3.z * Wreg[14]; u3 += b3.w * Wreg[15];
            u0 += b4.x * Wreg[16]; u1 += b4.y * Wreg[17]; u2 += b4.z * Wreg[18]; u3 += b4.w * Wreg[19];
            u0 += b5.x * Wreg[20]; u1 += b5.y * Wreg[21]; u2 += b5.z * Wreg[22]; u3 += b5.w * Wreg[23];
            u0 += b6.x * Wreg[24]; u1 += b6.y * Wreg[25]; u2 += b6.z * Wreg[26]; u3 += b6.w * Wreg[27];
            u0 += b7.x * Wreg[28]; u1 += b7.y * Wreg[29]; u2 += b7.z * Wreg[30]; u3 += b7.w * Wreg[31];

            int p0 = (e0 & 63) * CCH + lane;
            int p1 = (e1 & 63) * CCH + lane;
            acc[p0] += (t0 + t1) + (t2 + t3);
            acc[p1] += (u0 + u1) + (u2 + u3);
        }
        if (j < cntk) {
            int lo = __shfl_sync(0xffffffffu, ent0, j & 31);
            int hi = __shfl_sync(0xffffffffu, ent1, j & 31);
            int e  = (j < 32) ? lo : hi;
            const float4* fr = (const float4*)(fin + (size_t)(e >> 6) * CCH);
            float4 a0 = __ldg(fr + 0), a1 = __ldg(fr + 1), a2 = __ldg(fr + 2), a3 = __ldg(fr + 3);
            float4 a4 = __ldg(fr + 4), a5 = __ldg(fr + 5), a6 = __ldg(fr + 6), a7 = __ldg(fr + 7);
            float t0, t1, t2, t3;
            t0  = a0.x * Wreg[0];  t1  = a0.y * Wreg[1];  t2  = a0.z * Wreg[2];  t3  = a0.w * Wreg[3];
            t0 += a1.x * Wreg[4];  t1 += a1.y * Wreg[5];  t2 += a1.z * Wreg[6];  t3 += a1.w * Wreg[7];
            t0 += a2.x * Wreg[8];  t1 += a2.y * Wreg[9];  t2 += a2.z * Wreg[10]; t3 += a2.w * Wreg[11];
            t0 += a3.x * Wreg[12]; t1 += a3.y * Wreg[13]; t2 += a3.z * Wreg[14]; t3 += a3.w * Wreg[15];
            t0 += a4.x * Wreg[16]; t1 += a4.y * Wreg[17]; t2 += a4.z * Wreg[18]; t3 += a4.w * Wreg[19];
            t0 += a5.x * Wreg[20]; t1 += a5.y * Wreg[21]; t2 += a5.z * Wreg[22]; t3 += a5.w * Wreg[23];
            t0 += a6.x * Wreg[24]; t1 += a6.y * Wreg[25]; t2 += a6.z * Wreg[26]; t3 += a6.w * Wreg[27];
            t0 += a7.x * Wreg[28]; t1 += a7.y * Wreg[29]; t2 += a7.z * Wreg[30]; t3 += a7.w * Wreg[31];
            acc[(e & 63) * CCH + lane] += (t0 + t1) + (t2 + t3);
        }
    }

    // epilogue: coalesced 128B stores per point
    int base = tile * TILE;
    #pragma unroll 4
    for (int p = 0; p < TILE; p++) {
        int g = base + p;
        if (g >= MPTS) break;
        float v = acc[p * CCH + lane];
        if (RELU) v = fmaxf(v, 0.f);
        fout[(size_t)g * CCH + lane] = v;
    }
}

// ---------------- launch ----------------
extern "C" void kernel_launch(void* const* d_in, const int* in_sizes, int n_in,
                              void* d_out, int out_size) {
    const float* features = (const float*)d_in[0];
    const int*   coords   = (const int*)d_in[1];
    const float* W1 = (const float*)d_in[n_in - 3];
    const float* W2 = (const float*)d_in[n_in - 2];
    const float* W3 = (const float*)d_in[n_in - 1];
    float* out = (float*)d_out;

    int*   grid_ptr = nullptr;
    int*   tcnt_ptr = nullptr;
    float* x1_ptr   = nullptr;
    float* x2_ptr   = nullptr;
    cudaGetSymbolAddress((void**)&grid_ptr, g_grid);
    cudaGetSymbolAddress((void**)&tcnt_ptr, g_tcnt);
    cudaGetSymbolAddress((void**)&x1_ptr,   g_x1);
    cudaGetSymbolAddress((void**)&x2_ptr,   g_x2);

    cudaMemsetAsync(grid_ptr, 0xFF, (size_t)BATCH * S3 * sizeof(int));
    cudaMemsetAsync(tcnt_ptr, 0x00, (size_t)NTILES * NK * sizeof(int));

    {
        int threads = 256, blocks = (MPTS + threads - 1) / threads;
        scatter_kernel<<<blocks, threads>>>(coords);
        build_pairs_kernel<<<blocks, threads>>>(coords);
    }
    {
        int threads = 128;
        int blocks = (NTILES + 3) / 4;
        layer_kernel<true ><<<blocks, threads>>>(features, x1_ptr, W1);
        layer_kernel<true ><<<blocks, threads>>>(x1_ptr,   x2_ptr, W2);
        layer_kernel<false><<<blocks, threads>>>(x2_ptr,   out,    W3);
    }
    (void)in_sizes; (void)out_size;
}